// round 12
// baseline (speedup 1.0000x reference)
#include <cuda_runtime.h>
#include <cuda_bf16.h>
#include <math.h>
#include <stdint.h>

#define S_LEN   2048
#define D_MODEL 1024
#define NHEAD   16
#define DK      64
#define BATCH   2
#define MTOT    (BATCH * S_LEN)      // 4096
#define MB      (1024*1024)
#define LOG2E   1.4426950408889634f

using bf = __nv_bfloat16;

// ---------------- scratch (bf16 hi/lo split representations) ----------------
__device__ bf g_Xhi[MTOT * D_MODEL],  g_Xlo[MTOT * D_MODEL];    // input x
__device__ bf g_Whi[4 * MB],          g_Wlo[4 * MB];            // Wq,Wk,Wv,Wo
__device__ bf g_Qhi[BATCH*NHEAD*S_LEN*DK], g_Qlo[BATCH*NHEAD*S_LEN*DK]; // [B,H,S,dk] (pre-scaled by 1/8)
__device__ bf g_Khi[BATCH*NHEAD*S_LEN*DK], g_Klo[BATCH*NHEAD*S_LEN*DK]; // [B,H,S,dk]
__device__ bf g_VThi[BATCH*NHEAD*DK*S_LEN], g_VTlo[BATCH*NHEAD*DK*S_LEN]; // [B,H,dk,S]
__device__ bf g_Chi[MTOT * D_MODEL],  g_Clo[MTOT * D_MODEL];    // context [B,S,D]

// ---------------- helpers ----------------
__device__ __forceinline__ void mma_bf16(float* c, const uint32_t* a, const uint32_t* b) {
    asm volatile(
        "mma.sync.aligned.m16n8k16.row.col.f32.bf16.bf16.f32 "
        "{%0,%1,%2,%3}, {%4,%5,%6,%7}, {%8,%9}, {%0,%1,%2,%3};"
        : "+f"(c[0]), "+f"(c[1]), "+f"(c[2]), "+f"(c[3])
        : "r"(a[0]), "r"(a[1]), "r"(a[2]), "r"(a[3]), "r"(b[0]), "r"(b[1]));
}

// ldmatrix x4: four 8x8 b16 matrices; per-lane row address in saddr.
__device__ __forceinline__ void ldsm4(uint32_t* r, uint32_t saddr) {
    asm volatile("ldmatrix.sync.aligned.m8n8.x4.shared.b16 {%0,%1,%2,%3}, [%4];"
                 : "=r"(r[0]), "=r"(r[1]), "=r"(r[2]), "=r"(r[3]) : "r"(saddr));
}

__device__ __forceinline__ void cpa16(uint32_t dst, const void* src) {
    asm volatile("cp.async.cg.shared.global [%0], [%1], 16;" :: "r"(dst), "l"(src));
}
__device__ __forceinline__ void cp_commit() { asm volatile("cp.async.commit_group;"); }
template<int N> __device__ __forceinline__ void cp_wait() {
    asm volatile("cp.async.wait_group %0;" :: "n"(N)); }

__device__ __forceinline__ unsigned short bfbits(bf v) { return *(unsigned short*)&v; }

// split pair (x,y) into packed bf16x2 hi and lo words (elem0 = low half)
__device__ __forceinline__ void split2(float x, float y, uint32_t& hi, uint32_t& lo) {
    bf hx = __float2bfloat16_rn(x), hy = __float2bfloat16_rn(y);
    bf lx = __float2bfloat16_rn(x - __bfloat162float(hx));
    bf ly = __float2bfloat16_rn(y - __bfloat162float(hy));
    hi = (uint32_t)bfbits(hx) | ((uint32_t)bfbits(hy) << 16);
    lo = (uint32_t)bfbits(lx) | ((uint32_t)bfbits(ly) << 16);
}

// ---------------- pre-pass: fp32 -> bf16 hi/lo, all 5 tensors in one launch --
__global__ void split_all(const float4* __restrict__ x,  const float4* __restrict__ wq,
                          const float4* __restrict__ wk, const float4* __restrict__ wv,
                          const float4* __restrict__ wo,
                          uint2* __restrict__ xhi, uint2* __restrict__ xlo,
                          uint2* __restrict__ whi, uint2* __restrict__ wlo)
{
    const int NX = MTOT * D_MODEL / 4;       // 1048576 float4
    const int NW = MB / 4;                   // 262144 float4 per W
    const int total = NX + 4 * NW;
    for (int i = blockIdx.x * blockDim.x + threadIdx.x; i < total;
         i += gridDim.x * blockDim.x) {
        const float4* src; uint2 *dhi, *dlo; int j;
        if (i < NX) { src = x; dhi = xhi; dlo = xlo; j = i; }
        else {
            int k = i - NX; int z = k / NW; j = k - z * NW;
            src = (z == 0) ? wq : (z == 1) ? wk : (z == 2) ? wv : wo;
            dhi = whi + (size_t)z * NW; dlo = wlo + (size_t)z * NW;
        }
        float4 v = src[j];
        uint32_t h0, l0, h1, l1;
        split2(v.x, v.y, h0, l0);
        split2(v.z, v.w, h1, l1);
        dhi[j] = make_uint2(h0, h1);
        dlo[j] = make_uint2(l0, l1);
    }
}

// ---------------- GEMM core: C = A[M,K] @ W[N,K]^T  (bf16x3 on mma.sync) ----
// 128x128x32 block tile, 256 threads, warp tile 64x32 (2x4 warp grid).
#define GSA   40                       // smem half-stride
#define ARR   (128 * GSA)              // 5120 halves per array
#define BUFH  (4 * ARR)                // halves per buffer
#define GEMM_SMEM (2 * BUFH * 2)       // bytes = 81920

__device__ __forceinline__ void gemm_accum(
    const bf* __restrict__ Ahi, const bf* __restrict__ Alo,
    const bf* __restrict__ Bhi, const bf* __restrict__ Blo,
    int mBase, int nBase, bf* S, float c[4][4][4])
{
    const int tid = threadIdx.x;
    const int lane = tid & 31, w = tid >> 5;
    const int wm = w >> 2, wn = w & 3;           // warp grid 2x4
    const uint32_t sb = (uint32_t)__cvta_generic_to_shared(S);

    // ldmatrix lane-derived offsets
    const int a_r = lane & 15;                   // row in 16-row A tile
    const int a_c = (lane >> 4) * 8;             // k block 0/8
    const int b_r = ((lane >> 4) << 3) + (lane & 7);  // n row across 2 8-tiles
    const int b_c = ((lane >> 3) & 1) * 8;            // k block 0/8

    auto issue = [&](int stage, int buf) {
        const int kc = stage * 32;
#pragma unroll
        for (int i = 0; i < 2; i++) {
            int idx = tid + i * 256;             // 0..511
            int row = idx >> 2;                  // 0..127
            int k8  = (idx & 3) * 8;
            uint32_t db = sb + (uint32_t)(buf * BUFH + row * GSA + k8) * 2;
            cpa16(db,                 Ahi + (size_t)(mBase + row) * D_MODEL + kc + k8);
            cpa16(db + ARR * 2,       Alo + (size_t)(mBase + row) * D_MODEL + kc + k8);
            cpa16(db + 2 * ARR * 2,   Bhi + (size_t)(nBase + row) * D_MODEL + kc + k8);
            cpa16(db + 3 * ARR * 2,   Blo + (size_t)(nBase + row) * D_MODEL + kc + k8);
        }
        cp_commit();
    };

#pragma unroll
    for (int mi = 0; mi < 4; mi++)
#pragma unroll
        for (int ni = 0; ni < 4; ni++)
#pragma unroll
            for (int v = 0; v < 4; v++) c[mi][ni][v] = 0.f;

    issue(0, 0);
    int buf = 0;
    const int NSTAGE = D_MODEL / 32;             // 32

    for (int st = 0; st < NSTAGE; st++) {
        if (st + 1 < NSTAGE) { issue(st + 1, buf ^ 1); cp_wait<1>(); }
        else                 { cp_wait<0>(); }
        __syncthreads();

        const uint32_t aA = sb + (uint32_t)(buf * BUFH) * 2;   // A-hi base (bytes)
        const uint32_t aB = aA + 2 * ARR * 2;                  // B-hi base

#pragma unroll
        for (int ks = 0; ks < 2; ks++) {
            const int kb = ks * 16;
            uint32_t ahi[4][4], alo[4][4];
#pragma unroll
            for (int mi = 0; mi < 4; mi++) {
                uint32_t ar = aA + (uint32_t)((wm * 64 + mi * 16 + a_r) * GSA + kb + a_c) * 2;
                ldsm4(ahi[mi], ar);
                ldsm4(alo[mi], ar + ARR * 2);
            }
#pragma unroll
            for (int np = 0; np < 2; np++) {     // n-tile pairs (0,1) and (2,3)
                uint32_t br = aB + (uint32_t)((wn * 32 + np * 16 + b_r) * GSA + kb + b_c) * 2;
                uint32_t bhi[4], blo[4];
                ldsm4(bhi, br);
                ldsm4(blo, br + ARR * 2);
#pragma unroll
                for (int q = 0; q < 2; q++) {
                    const int ni = np * 2 + q;
#pragma unroll
                    for (int mi = 0; mi < 4; mi++) {
                        mma_bf16(c[mi][ni], ahi[mi], bhi + q * 2);
                        mma_bf16(c[mi][ni], ahi[mi], blo + q * 2);
                        mma_bf16(c[mi][ni], alo[mi], bhi + q * 2);
                    }
                }
            }
        }
        __syncthreads();
        buf ^= 1;
    }
}

// Fused Q/K/V projection: blockIdx.z selects weight/output. Q pre-scaled by 1/8.
// V epilogue stages the transpose through smem -> coalesced 256B global stores.
#define SST 136                        // staging half-stride (272B rows, 16B-aligned)

__global__ __launch_bounds__(256, 2)
void gemm_qkv(const bf* __restrict__ Ahi, const bf* __restrict__ Alo,
              const bf* __restrict__ Whi, const bf* __restrict__ Wlo)
{
    extern __shared__ bf S[];
    float c[4][4][4];
    const int z = blockIdx.z;
    const int mBase = blockIdx.y * 128, nBase = blockIdx.x * 128;
    gemm_accum(Ahi, Alo, Whi + (size_t)z * MB, Wlo + (size_t)z * MB,
               mBase, nBase, S, c);

    const int tid = threadIdx.x;
    const int lane = tid & 31, w = tid >> 5;
    const int wm = w >> 2, wn = w & 3;
    const int g = lane >> 2, c2 = (lane & 3) * 2;

    if (z < 2) {
        bf* dsthi = (z == 0) ? g_Qhi : g_Khi;
        bf* dstlo = (z == 0) ? g_Qlo : g_Klo;
        const float qs = (z == 0) ? 0.125f : 1.0f;   // fold 1/sqrt(dk) into Q
#pragma unroll
        for (int mi = 0; mi < 4; mi++) {
#pragma unroll
            for (int ni = 0; ni < 4; ni++) {
                int m = mBase + wm * 64 + mi * 16 + g;
                int n = nBase + wn * 32 + ni * 8 + c2;
                int b = m >> 11, s = m & (S_LEN - 1);
                int h = n >> 6, d = n & 63;
                size_t o = (((size_t)(b * NHEAD + h)) * S_LEN + s) * DK + d;
                uint32_t hi, lo;
                split2(c[mi][ni][0] * qs, c[mi][ni][1] * qs, hi, lo);
                *(uint32_t*)&dsthi[o] = hi; *(uint32_t*)&dstlo[o] = lo;
                split2(c[mi][ni][2] * qs, c[mi][ni][3] * qs, hi, lo);
                *(uint32_t*)&dsthi[o + 8 * DK] = hi; *(uint32_t*)&dstlo[o + 8 * DK] = lo;
            }
        }
    } else {
        // ---- V: stage transposed tile [n][m] in smem (bf16 hi/lo planes) ----
        bf* sVhi = S;
        bf* sVlo = S + 128 * SST;
#pragma unroll
        for (int mi = 0; mi < 4; mi++) {
#pragma unroll
            for (int ni = 0; ni < 4; ni++) {
                int m0 = wm * 64 + mi * 16 + g;
                int n0 = wn * 32 + ni * 8 + c2;
#pragma unroll
                for (int v = 0; v < 4; v++) {
                    int nn = n0 + (v & 1);
                    int mm = m0 + (v >> 1) * 8;
                    float val = c[mi][ni][v];
                    bf hv = __float2bfloat16_rn(val);
                    bf lv = __float2bfloat16_rn(val - __bfloat162float(hv));
                    sVhi[nn * SST + mm] = hv;
                    sVlo[nn * SST + mm] = lv;
                }
            }
        }
        __syncthreads();
        // ---- coalesced copy-out: one 128-half row per thread ----
        const int r = tid;                        // 0..255 (128 hi rows + 128 lo rows)
        const int nloc = (r < 128) ? r : r - 128;
        const bf* srow = ((r < 128) ? sVhi : sVlo) + nloc * SST;
        bf* dbase = (r < 128) ? g_VThi : g_VTlo;
        const int nglob = nBase + nloc;
        const int h = nglob >> 6, d = nglob & 63;
        const int bb = mBase >> 11, s0 = mBase & (S_LEN - 1);
        bf* drow = dbase + (((size_t)(bb * NHEAD + h)) * DK + d) * S_LEN + s0;
#pragma unroll
        for (int t2 = 0; t2 < 16; t2++) {
            uint4 vv = *(const uint4*)(srow + t2 * 8);
            *(uint4*)(drow + t2 * 8) = vv;
        }
    }
}

// Output projection: context(bf16 hi/lo) @ Wo^T -> fp32 out [M,N]
__global__ __launch_bounds__(256, 2)
void gemm_out(const bf* __restrict__ Whi, const bf* __restrict__ Wlo,
              float* __restrict__ out)
{
    extern __shared__ bf S[];
    float c[4][4][4];
    const int mBase = blockIdx.y * 128, nBase = blockIdx.x * 128;
    gemm_accum(g_Chi, g_Clo, Whi + (size_t)3 * MB, Wlo + (size_t)3 * MB,
               mBase, nBase, S, c);

    const int lane = threadIdx.x & 31, w = threadIdx.x >> 5;
    const int wm = w >> 2, wn = w & 3;
    const int g = lane >> 2, c2 = (lane & 3) * 2;

#pragma unroll
    for (int mi = 0; mi < 4; mi++) {
#pragma unroll
        for (int ni = 0; ni < 4; ni++) {
            int m = mBase + wm * 64 + mi * 16 + g;
            int n = nBase + wn * 32 + ni * 8 + c2;
            *(float2*)&out[(size_t)m * D_MODEL + n] =
                make_float2(c[mi][ni][0], c[mi][ni][1]);
            *(float2*)&out[(size_t)(m + 8) * D_MODEL + n] =
                make_float2(c[mi][ni][2], c[mi][ni][3]);
        }
    }
}

// ---------------- Flash attention (mma.sync), causal -------------------------
// Br=128, Bc=64, 256 threads, 8 warps; warp owns a 16-row strip.
// P kept in registers; K/V double-buffered cp.async; ldmatrix operand loads.
#define ASA 72                                // half stride
#define QH_OFF  0
#define QL_OFF  (128 * ASA)                   // 9216
#define ST_OFF  (2 * 128 * ASA)               // 18432
#define ST_SZ   (4 * 64 * ASA)                // 18432 halves per stage
#define ATTN_SMEM ((ST_OFF + 2 * ST_SZ) * 2)  // 110592 bytes

__global__ __launch_bounds__(256, 2)
void attn_tc(const bf* __restrict__ Qhi_g, const bf* __restrict__ Qlo_g,
             const bf* __restrict__ Khi_g, const bf* __restrict__ Klo_g,
             const bf* __restrict__ VThi_g, const bf* __restrict__ VTlo_g)
{
    extern __shared__ bf S[];
    const int tid = threadIdx.x;
    const int lane = tid & 31, w = tid >> 5;
    const int g = lane >> 2, c2 = (lane & 3) * 2;
    const int qt = (int)gridDim.x - 1 - (int)blockIdx.x;   // largest-first
    const int bh = blockIdx.y;
    const int q0 = qt * 128;
    const uint32_t sb = (uint32_t)__cvta_generic_to_shared(S);

    // ldmatrix lane-derived offsets
    const int a_r = lane & 15;
    const int a_c = (lane >> 4) * 8;
    const int b_r = ((lane >> 4) << 3) + (lane & 7);
    const int b_c = ((lane >> 3) & 1) * 8;

    const bf* Qhi = Qhi_g + (size_t)bh * S_LEN * DK;
    const bf* Qlo = Qlo_g + (size_t)bh * S_LEN * DK;
    const bf* Khi = Khi_g + (size_t)bh * S_LEN * DK;
    const bf* Klo = Klo_g + (size_t)bh * S_LEN * DK;
    const bf* VThi = VThi_g + (size_t)bh * DK * S_LEN;
    const bf* VTlo = VTlo_g + (size_t)bh * DK * S_LEN;

    auto issueKV = [&](int jt, int stage) {
        const int j0 = jt * 64;
        const uint32_t base = sb + (uint32_t)(ST_OFF + stage * ST_SZ) * 2;
#pragma unroll
        for (int i = 0; i < 2; i++) {
            int idx = tid + i * 256;              // 0..511
            int row = idx >> 3, d8 = (idx & 7) * 8;
            uint32_t db = base + (uint32_t)(row * ASA + d8) * 2;
            cpa16(db,                    Khi + (size_t)(j0 + row) * DK + d8);
            cpa16(db + 4608 * 2,         Klo + (size_t)(j0 + row) * DK + d8);
            cpa16(db + 9216 * 2,         VThi + (size_t)row * S_LEN + j0 + d8);
            cpa16(db + 13824 * 2,        VTlo + (size_t)row * S_LEN + j0 + d8);
        }
        cp_commit();
    };

    // group 0: Q tile (128 x 64 halves, hi+lo)
#pragma unroll
    for (int i = 0; i < 4; i++) {
        int idx = tid + i * 256;                  // 0..1023
        int row = idx >> 3, d8 = (idx & 7) * 8;
        uint32_t db = sb + (uint32_t)(row * ASA + d8) * 2;
        cpa16(db + QH_OFF * 2, Qhi + (size_t)(q0 + row) * DK + d8);
        cpa16(db + QL_OFF * 2, Qlo + (size_t)(q0 + row) * DK + d8);
    }
    cp_commit();

    const int jt_max = 2 * qt + 1;
    issueKV(0, 0);
    if (jt_max >= 1) issueKV(1, 1);

    float o_acc[8][4];
#pragma unroll
    for (int nt = 0; nt < 8; nt++)
#pragma unroll
        for (int v = 0; v < 4; v++) o_acc[nt][v] = 0.f;
    float m_a = -1e30f, m_b = -1e30f, l_a = 0.f, l_b = 0.f;

    const int growA = q0 + 16 * w + g;
    const int growB = growA + 8;

    for (int jt = 0; jt <= jt_max; jt++) {
        const int j0 = jt * 64;
        const int stage = jt & 1;
        const int KH = ST_OFF + stage * ST_SZ;
        const int KL = KH + 4608;
        const int VH = KH + 9216;
        const int VL = KH + 13824;

        if (jt == jt_max) cp_wait<0>(); else cp_wait<1>();
        __syncthreads();

        // ---- S = Q K^T (Q pre-scaled by 1/8) ----
        float sc[8][4];
#pragma unroll
        for (int nt = 0; nt < 8; nt++)
#pragma unroll
            for (int v = 0; v < 4; v++) sc[nt][v] = 0.f;

#pragma unroll
        for (int ks = 0; ks < 4; ks++) {
            const int kb = ks * 16;
            uint32_t qaddr = sb + (uint32_t)((16 * w + a_r) * ASA + kb + a_c) * 2;
            uint32_t ahi[4], alo[4];
            ldsm4(ahi, qaddr + QH_OFF * 2);
            ldsm4(alo, qaddr + QL_OFF * 2);
#pragma unroll
            for (int np = 0; np < 4; np++) {      // n-tile pairs
                uint32_t kaddr = sb + (uint32_t)((np * 16 + b_r) * ASA + kb + b_c) * 2;
                uint32_t bhi[4], blo[4];
                ldsm4(bhi, kaddr + KH * 2);
                ldsm4(blo, kaddr + KL * 2);
#pragma unroll
                for (int q = 0; q < 2; q++) {
                    const int nt = np * 2 + q;
                    mma_bf16(sc[nt], ahi, bhi + q * 2);
                    mma_bf16(sc[nt], ahi, blo + q * 2);
                    mma_bf16(sc[nt], alo, bhi + q * 2);
                }
            }
        }

        // ---- softmax (warp-local) + pack P into A-operand registers ----
        const bool diag = (jt >= 2 * qt);
        float mA = -1e30f, mB = -1e30f;
#pragma unroll
        for (int nt = 0; nt < 8; nt++) {
            int col = j0 + nt * 8 + c2;
            if (diag) {
                if (col     > growA) sc[nt][0] = -1e30f;
                if (col + 1 > growA) sc[nt][1] = -1e30f;
                if (col     > growB) sc[nt][2] = -1e30f;
                if (col + 1 > growB) sc[nt][3] = -1e30f;
            }
            mA = fmaxf(mA, fmaxf(sc[nt][0], sc[nt][1]));
            mB = fmaxf(mB, fmaxf(sc[nt][2], sc[nt][3]));
        }
#pragma unroll
        for (int o = 1; o < 4; o <<= 1) {
            mA = fmaxf(mA, __shfl_xor_sync(0xffffffffu, mA, o, 4));
            mB = fmaxf(mB, __shfl_xor_sync(0xffffffffu, mB, o, 4));
        }
        float mxA = fmaxf(m_a, mA), mxB = fmaxf(m_b, mB);
        float cfA = exp2f((m_a - mxA) * LOG2E);
        float cfB = exp2f((m_b - mxB) * LOG2E);
        float rsA = 0.f, rsB = 0.f;
        uint32_t pa_hi[8], pa_lo[8], pb_hi[8], pb_lo[8];  // rows g / g+8
#pragma unroll
        for (int nt = 0; nt < 8; nt++) {
            float p0 = exp2f((sc[nt][0] - mxA) * LOG2E);
            float p1 = exp2f((sc[nt][1] - mxA) * LOG2E);
            float p2 = exp2f((sc[nt][2] - mxB) * LOG2E);
            float p3 = exp2f((sc[nt][3] - mxB) * LOG2E);
            rsA += p0 + p1; rsB += p2 + p3;
            split2(p0, p1, pa_hi[nt], pa_lo[nt]);
            split2(p2, p3, pb_hi[nt], pb_lo[nt]);
        }
#pragma unroll
        for (int o = 1; o < 4; o <<= 1) {
            rsA += __shfl_xor_sync(0xffffffffu, rsA, o, 4);
            rsB += __shfl_xor_sync(0xffffffffu, rsB, o, 4);
        }
        l_a = l_a * cfA + rsA;  m_a = mxA;
        l_b = l_b * cfB + rsB;  m_b = mxB;
#pragma unroll
        for (int nt = 0; nt < 8; nt++) {
            o_acc[nt][0] *= cfA; o_acc[nt][1] *= cfA;
            o_acc[nt][2] *= cfB; o_acc[nt][3] *= cfB;
        }

        // ---- O += P V  (P from registers, V^T via ldmatrix) ----
#pragma unroll
        for (int ks = 0; ks < 4; ks++) {
            const int kb = ks * 16;
            uint32_t ahi[4] = {pa_hi[2*ks], pb_hi[2*ks], pa_hi[2*ks+1], pb_hi[2*ks+1]};
            uint32_t alo[4] = {pa_lo[2*ks], pb_lo[2*ks], pa_lo[2*ks+1], pb_lo[2*ks+1]};
#pragma unroll
            for (int np = 0; np < 4; np++) {
                uint32_t vaddr = sb + (uint32_t)((np * 16 + b_r) * ASA + kb + b_c) * 2;
                uint32_t bhi[4], blo[4];
                ldsm4(bhi, vaddr + VH * 2);
                ldsm4(blo, vaddr + VL * 2);
#pragma unroll
                for (int q = 0; q < 2; q++) {
                    const int nt = np * 2 + q;
                    mma_bf16(o_acc[nt], ahi, bhi + q * 2);
                    mma_bf16(o_acc[nt], ahi, blo + q * 2);
                    mma_bf16(o_acc[nt], alo, bhi + q * 2);
                }
            }
        }

        __syncthreads();                          // all warps done with this stage
        if (jt + 2 <= jt_max) issueKV(jt + 2, stage);
    }

    // ---- epilogue: normalize, split to bf16 hi/lo context [B,S,D] ----
    const float invA = 1.f / l_a, invB = 1.f / l_b;
    const int b = bh >> 4, h = bh & 15;
    const int sA = q0 + 16 * w + g;
#pragma unroll
    for (int nt = 0; nt < 8; nt++) {
        int col = h * DK + nt * 8 + c2;
        uint32_t hi, lo;
        split2(o_acc[nt][0] * invA, o_acc[nt][1] * invA, hi, lo);
        size_t o = ((size_t)(b * S_LEN + sA)) * D_MODEL + col;
        *(uint32_t*)&g_Chi[o] = hi; *(uint32_t*)&g_Clo[o] = lo;
        split2(o_acc[nt][2] * invB, o_acc[nt][3] * invB, hi, lo);
        size_t o2 = ((size_t)(b * S_LEN + sA + 8)) * D_MODEL + col;
        *(uint32_t*)&g_Chi[o2] = hi; *(uint32_t*)&g_Clo[o2] = lo;
    }
}

// ---------------------------------------------------------------------------
extern "C" void kernel_launch(void* const* d_in, const int* in_sizes, int n_in,
                              void* d_out, int out_size)
{
    const float* x  = (const float*)d_in[0];
    const float* Wq = (const float*)d_in[1];
    const float* Wk = (const float*)d_in[2];
    const float* Wv = (const float*)d_in[3];
    const float* Wo = (const float*)d_in[4];
    float* out = (float*)d_out;

    bf *pXhi, *pXlo, *pWhi, *pWlo;
    bf *pQhi, *pQlo, *pKhi, *pKlo, *pVThi, *pVTlo;
    cudaGetSymbolAddress((void**)&pXhi, g_Xhi);
    cudaGetSymbolAddress((void**)&pXlo, g_Xlo);
    cudaGetSymbolAddress((void**)&pWhi, g_Whi);
    cudaGetSymbolAddress((void**)&pWlo, g_Wlo);
    cudaGetSymbolAddress((void**)&pQhi, g_Qhi);
    cudaGetSymbolAddress((void**)&pQlo, g_Qlo);
    cudaGetSymbolAddress((void**)&pKhi, g_Khi);
    cudaGetSymbolAddress((void**)&pKlo, g_Klo);
    cudaGetSymbolAddress((void**)&pVThi, g_VThi);
    cudaGetSymbolAddress((void**)&pVTlo, g_VTlo);

    static bool configured = false;
    if (!configured) {
        cudaFuncSetAttribute(gemm_qkv, cudaFuncAttributeMaxDynamicSharedMemorySize, GEMM_SMEM);
        cudaFuncSetAttribute(gemm_out, cudaFuncAttributeMaxDynamicSharedMemorySize, GEMM_SMEM);
        cudaFuncSetAttribute(attn_tc,  cudaFuncAttributeMaxDynamicSharedMemorySize, ATTN_SMEM);
        configured = true;
    }

    // pre-pass: split all inputs into bf16 hi/lo (single launch)
    split_all<<<4096, 256>>>((const float4*)x, (const float4*)Wq, (const float4*)Wk,
                             (const float4*)Wv, (const float4*)Wo,
                             (uint2*)pXhi, (uint2*)pXlo, (uint2*)pWhi, (uint2*)pWlo);

    dim3 qkvGrid(D_MODEL / 128, MTOT / 128, 3);   // (8, 32, 3)
    gemm_qkv<<<qkvGrid, 256, GEMM_SMEM>>>(pXhi, pXlo, pWhi, pWlo);

    dim3 aGrid(S_LEN / 128, BATCH * NHEAD);       // (16, 32)
    attn_tc<<<aGrid, 256, ATTN_SMEM>>>(pQhi, pQlo, pKhi, pKlo, pVThi, pVTlo);

    dim3 oGrid(D_MODEL / 128, MTOT / 128);        // (8, 32)
    gemm_out<<<oGrid, 256, GEMM_SMEM>>>(pWhi, pWlo, out);
}